// round 6
// baseline (speedup 1.0000x reference)
#include <cuda_runtime.h>

#define HW     512
#define NB     16
#define PLANE  (HW * HW)          // 262144
#define NPIX   (NB * PLANE)       // 4194304

// Global scratch (2 planes + small reductions)
__device__ float g_M[NPIX];        // local mean m
__device__ float g_S[NPIX];        // sigma
__device__ float g_part[NB * 64];  // per-block sigma partial sums (8x8 blocks/batch)

// packed fp32x2 FMA: d += a * b (two independent lanes)
__device__ __forceinline__ void ffma2(float2 &d, const float2 a, const float2 b) {
    asm("fma.rn.f32x2 %0, %1, %2, %0;"
        : "+l"(reinterpret_cast<unsigned long long &>(d))
        : "l"(reinterpret_cast<const unsigned long long &>(a)),
          "l"(reinterpret_cast<const unsigned long long &>(b)));
}

// 4x4-output 9x9 conv micro-tile with packed filter pairs + 4-row sliding window.
// base points at input tile element (row0, col0); stride in floats.
// sfp layout per tap-row t: [0..4]=(f2k,f2k+1), [5..8]=(f2k+1,f2k+2), [9]=(0,f0)
__device__ __forceinline__ void conv16(const float* base, const int stride,
                                       const float2* __restrict__ sfp,
                                       float2 acc[4][4]) {
    #pragma unroll
    for (int i = 0; i < 4; ++i)
        #pragma unroll
        for (int j = 0; j < 4; ++j) acc[i][j] = make_float2(0.f, 0.f);

    float2 W[4][6];
    #pragma unroll
    for (int j = 0; j < 4; ++j) {
        const float* p = base + j * stride;
        float4 a = *(const float4*)p, bb = *(const float4*)(p + 4), c = *(const float4*)(p + 8);
        W[j][0] = make_float2(a.x, a.y);   W[j][1] = make_float2(a.z, a.w);
        W[j][2] = make_float2(bb.x, bb.y); W[j][3] = make_float2(bb.z, bb.w);
        W[j][4] = make_float2(c.x, c.y);   W[j][5] = make_float2(c.z, c.w);
    }
    #pragma unroll
    for (int t = 0; t < 9; ++t) {
        const float2* fp = &sfp[t * 10];
        float2 fe0 = fp[0], fe1 = fp[1], fe2 = fp[2], fe3 = fp[3], fe4 = fp[4];
        float2 fo0 = fp[5], fo1 = fp[6], fo2 = fp[7], fo3 = fp[8], f0z = fp[9];
        #pragma unroll
        for (int oy = 0; oy < 4; ++oy) {
            float2* w = W[(t + oy) & 3];
            ffma2(acc[oy][0], fe0, w[0]); ffma2(acc[oy][0], fe1, w[1]);
            ffma2(acc[oy][0], fe2, w[2]); ffma2(acc[oy][0], fe3, w[3]);
            ffma2(acc[oy][0], fe4, w[4]);
            ffma2(acc[oy][2], fe0, w[1]); ffma2(acc[oy][2], fe1, w[2]);
            ffma2(acc[oy][2], fe2, w[3]); ffma2(acc[oy][2], fe3, w[4]);
            ffma2(acc[oy][2], fe4, w[5]);
            ffma2(acc[oy][1], f0z, w[0]); ffma2(acc[oy][1], fo0, w[1]);
            ffma2(acc[oy][1], fo1, w[2]); ffma2(acc[oy][1], fo2, w[3]);
            ffma2(acc[oy][1], fo3, w[4]);
            ffma2(acc[oy][3], f0z, w[1]); ffma2(acc[oy][3], fo0, w[2]);
            ffma2(acc[oy][3], fo1, w[3]); ffma2(acc[oy][3], fo2, w[4]);
            ffma2(acc[oy][3], fo3, w[5]);
        }
        if (t < 8) {
            const float* p = base + (t + 4) * stride;
            float4 a = *(const float4*)p, bb = *(const float4*)(p + 4), c = *(const float4*)(p + 8);
            float2* w = W[t & 3];
            w[0] = make_float2(a.x, a.y);   w[1] = make_float2(a.z, a.w);
            w[2] = make_float2(bb.x, bb.y); w[3] = make_float2(bb.z, bb.w);
            w[4] = make_float2(c.x, c.y);   w[5] = make_float2(c.z, c.w);
        }
    }
}

// ---------------------------------------------------------------------------
// Fused kernel: filter normalize + S1/S2 + conv0 (72x72, in smem) + t
//               + conv1 (64x64) -> sigma, m, block partial sums.
// Block 256 threads, 64x64 outputs, grid (8, 8, NB).
// ---------------------------------------------------------------------------
__global__ void __launch_bounds__(256) k_fused(const float* __restrict__ x,
                                               const float* __restrict__ filt) {
    __shared__ float  tileA[80 * 80];   // S1, stride 80
    __shared__ float  tileB[72 * 76];   // S2, then t, stride 76
    __shared__ float2 sfp[90];
    __shared__ float  red[3];
    __shared__ float  wsum[8];

    const int b   = blockIdx.z;
    const int bx  = blockIdx.x;
    const int by  = blockIdx.y;
    const int tid = threadIdx.x;
    const int x0  = bx * 64 - 8;        // S1 tile origin
    const int y0  = by * 64 - 8;

    // ---- inline filter sum (threads 0..95, 3 warps) ----
    if (tid < 96) {
        float v = (tid < 81) ? (__ldg(&filt[tid]) + 10.0f) : 0.0f;
        #pragma unroll
        for (int o = 16; o; o >>= 1) v += __shfl_xor_sync(0xffffffffu, v, o);
        if ((tid & 31) == 0) red[tid >> 5] = v;
    }
    __syncthreads();
    {
        float inv = 1.0f / (red[0] + red[1] + red[2]);
        if (tid < 90) {
            int r = tid / 10, k = tid - r * 10;
            const float* f = filt + r * 9;
            float2 o;
            if (k < 5) {
                float a = (__ldg(&f[2 * k]) + 10.0f) * inv;
                float bb = (2 * k + 1 < 9) ? (__ldg(&f[2 * k + 1]) + 10.0f) * inv : 0.0f;
                o = make_float2(a, bb);
            } else if (k < 9) {
                int j = k - 5;
                o = make_float2((__ldg(&f[2 * j + 1]) + 10.0f) * inv,
                                (__ldg(&f[2 * j + 2]) + 10.0f) * inv);
            } else {
                o = make_float2(0.0f, (__ldg(&f[0]) + 10.0f) * inv);
            }
            sfp[tid] = o;
        }
    }

    // ---- load x tile: S1 (80x80) + S2 (center 72x72) ----
    for (int i = tid; i < 80 * 20; i += 256) {
        int row = i / 20, q = i - row * 20;
        int gy = y0 + row, gx = x0 + q * 4;
        float4 a = make_float4(0.f, 0.f, 0.f, 0.f), bb = a, c = a;
        if ((unsigned)gy < (unsigned)HW && (unsigned)gx < (unsigned)HW) {
            const float4* p = (const float4*)x +
                (((size_t)b * PLANE + (size_t)gy * HW + gx) >> 2) * 3;
            a = p[0]; bb = p[1]; c = p[2];
        }
        float4 s1, s2;
        s1.x = a.x + a.y + a.z;   s2.x = a.x*a.x + a.y*a.y + a.z*a.z;
        s1.y = a.w + bb.x + bb.y; s2.y = a.w*a.w + bb.x*bb.x + bb.y*bb.y;
        s1.z = bb.z + bb.w + c.x; s2.z = bb.z*bb.z + bb.w*bb.w + c.x*c.x;
        s1.w = c.y + c.z + c.w;   s2.w = c.y*c.y + c.z*c.z + c.w*c.w;
        *(float4*)&tileA[row * 80 + q * 4] = s1;
        if (row >= 4 && row < 76 && q >= 1 && q < 19)
            *(float4*)&tileB[(row - 4) * 76 + (q - 1) * 4] = s2;
    }
    __syncthreads();

    // ---- phase B: conv0 at 72x72 t-points; t = S2 - 2 m S1 + 3 m^2 (in-place) ----
    #pragma unroll 1
    for (int pass = 0; pass < 2; ++pass) {
        int tt = tid + pass * 256;
        if (tt < 324) {
            int ti = tt % 18, tj = tt / 18;
            float2 acc[4][4];
            conv16(&tileA[(tj * 4) * 80 + ti * 4], 80, sfp, acc);
            int gx0 = bx * 64 - 4 + ti * 4;
            bool vx0 = (unsigned)(gx0 + 0) < (unsigned)HW;
            bool vx1 = (unsigned)(gx0 + 1) < (unsigned)HW;
            bool vx2 = (unsigned)(gx0 + 2) < (unsigned)HW;
            bool vx3 = (unsigned)(gx0 + 3) < (unsigned)HW;
            bool mcol = (ti >= 1 && ti < 17);
            #pragma unroll
            for (int oy = 0; oy < 4; ++oy) {
                int r  = tj * 4 + oy;
                int gy = by * 64 - 4 + r;
                bool vy = (unsigned)gy < (unsigned)HW;
                float m0 = acc[oy][0].x + acc[oy][0].y;
                float m1 = acc[oy][1].x + acc[oy][1].y;
                float m2 = acc[oy][2].x + acc[oy][2].y;
                float m3 = acc[oy][3].x + acc[oy][3].y;
                float4 s2 = *(const float4*)&tileB[r * 76 + ti * 4];
                float4 s1 = *(const float4*)&tileA[(r + 4) * 80 + ti * 4 + 4];
                float4 t4;
                t4.x = (vy && vx0) ? s2.x - 2.0f*m0*s1.x + 3.0f*m0*m0 : 0.0f;
                t4.y = (vy && vx1) ? s2.y - 2.0f*m1*s1.y + 3.0f*m1*m1 : 0.0f;
                t4.z = (vy && vx2) ? s2.z - 2.0f*m2*s1.z + 3.0f*m2*m2 : 0.0f;
                t4.w = (vy && vx3) ? s2.w - 2.0f*m3*s1.w + 3.0f*m3*m3 : 0.0f;
                *(float4*)&tileB[r * 76 + ti * 4] = t4;
                if (mcol && r >= 4 && r < 68) {
                    size_t q = ((size_t)b * PLANE +
                                (size_t)(by * 64 + r - 4) * HW + (gx0 + 4 - 4)) >> 2;
                    ((float4*)g_M)[q] = make_float4(m0, m1, m2, m3);
                }
            }
        }
    }
    __syncthreads();

    // ---- phase C: conv1 over t -> sigma + partial sums ----
    {
        const int tx = tid & 15;
        const int ty = tid >> 4;
        float2 acc[4][4];
        conv16(&tileB[(ty * 4) * 76 + tx * 4], 76, sfp, acc);

        const int ox = bx * 64 + tx * 4;
        float local = 0.0f;
        #pragma unroll
        for (int oy = 0; oy < 4; ++oy) {
            int oyg = by * 64 + ty * 4 + oy;
            size_t q = ((size_t)b * PLANE + (size_t)oyg * HW + ox) >> 2;
            float4 sg;
            sg.x = sqrtf(fmaxf(acc[oy][0].x + acc[oy][0].y, 0.0f));
            sg.y = sqrtf(fmaxf(acc[oy][1].x + acc[oy][1].y, 0.0f));
            sg.z = sqrtf(fmaxf(acc[oy][2].x + acc[oy][2].y, 0.0f));
            sg.w = sqrtf(fmaxf(acc[oy][3].x + acc[oy][3].y, 0.0f));
            ((float4*)g_S)[q] = sg;
            local += sg.x + sg.y + sg.z + sg.w;
        }
        #pragma unroll
        for (int o = 16; o; o >>= 1) local += __shfl_xor_sync(0xffffffffu, local, o);
        if ((tid & 31) == 0) wsum[tid >> 5] = local;
        __syncthreads();
        if (tid == 0) {
            float s = 0.0f;
            #pragma unroll
            for (int k = 0; k < 8; ++k) s += wsum[k];
            g_part[b * 64 + by * 8 + bx] = s;
        }
    }
}

// ---------------------------------------------------------------------------
// Final: per-block redundant mean reduce (64 partials) + normalize + write out
// Block = 256 threads = 256 pixel-quads; 256 blocks per batch.
// ---------------------------------------------------------------------------
__global__ void __launch_bounds__(256) k_final(const float* __restrict__ x,
                                               float* __restrict__ out) {
    __shared__ float ws[2];
    __shared__ float smean;
    const int tid = threadIdx.x;
    const int b   = blockIdx.x >> 8;            // 256 blocks per batch

    if (tid < 64) {
        float v = g_part[b * 64 + tid];
        #pragma unroll
        for (int o = 16; o; o >>= 1) v += __shfl_xor_sync(0xffffffffu, v, o);
        if ((tid & 31) == 0) ws[tid >> 5] = v;
    }
    __syncthreads();
    if (tid == 0) smean = (ws[0] + ws[1]) * (1.0f / (float)PLANE);
    __syncthreads();
    const float mean = smean;

    int i = blockIdx.x * 256 + tid;              // pixel-quad index
    float4 m  = ((const float4*)g_M)[i];
    float4 sg = ((const float4*)g_S)[i];
    float r0 = 1.0f / fmaxf(mean, sg.x);
    float r1 = 1.0f / fmaxf(mean, sg.y);
    float r2 = 1.0f / fmaxf(mean, sg.z);
    float r3 = 1.0f / fmaxf(mean, sg.w);

    const float4* xp = (const float4*)x;
    float4 a  = xp[i * 3 + 0];
    float4 bb = xp[i * 3 + 1];
    float4 c  = xp[i * 3 + 2];

    float4 o0, o1, o2;
    o0.x = (a.x  - m.x) * r0;  o0.y = (a.y  - m.x) * r0;  o0.z = (a.z  - m.x) * r0;
    o0.w = (a.w  - m.y) * r1;
    o1.x = (bb.x - m.y) * r1;  o1.y = (bb.y - m.y) * r1;
    o1.z = (bb.z - m.z) * r2;  o1.w = (bb.w - m.z) * r2;
    o2.x = (c.x  - m.z) * r2;
    o2.y = (c.y  - m.w) * r3;  o2.z = (c.z  - m.w) * r3;  o2.w = (c.w  - m.w) * r3;

    float4* op = (float4*)out;
    op[i * 3 + 0] = o0;
    op[i * 3 + 1] = o1;
    op[i * 3 + 2] = o2;
}

// ---------------------------------------------------------------------------
extern "C" void kernel_launch(void* const* d_in, const int* in_sizes, int n_in,
                              void* d_out, int out_size) {
    const float* x    = (const float*)d_in[0];
    const float* filt = (const float*)d_in[1];
    float* out        = (float*)d_out;

    dim3 cgrid(8, 8, NB);
    k_fused<<<cgrid, 256>>>(x, filt);
    k_final<<<NPIX / 1024, 256>>>(x, out);
}

// round 7
// speedup vs baseline: 1.0070x; 1.0070x over previous
#include <cuda_runtime.h>

#define HW     512
#define NB     16
#define PLANE  (HW * HW)          // 262144
#define NPIX   (NB * PLANE)       // 4194304

// Global scratch (2 planes + small reductions)
__device__ float g_M[NPIX];        // local mean m
__device__ float g_S[NPIX];        // sigma
__device__ float g_part[NB * 64];  // per-block sigma partial sums (8x8 blocks/batch)

// packed fp32x2 FMA: d += a * b (two independent lanes)
__device__ __forceinline__ void ffma2(float2 &d, const float2 a, const float2 b) {
    asm("fma.rn.f32x2 %0, %1, %2, %0;"
        : "+l"(reinterpret_cast<unsigned long long &>(d))
        : "l"(reinterpret_cast<const unsigned long long &>(a)),
          "l"(reinterpret_cast<const unsigned long long &>(b)));
}

// 4x4-output 9x9 conv micro-tile with packed filter pairs + 4-row sliding window.
// base points at input tile element (row0, col0); stride in floats.
// sfp layout per tap-row t: [0..4]=(f2k,f2k+1), [5..8]=(f2k+1,f2k+2), [9]=(0,f0)
__device__ __forceinline__ void conv16(const float* base, const int stride,
                                       const float2* __restrict__ sfp,
                                       float2 acc[4][4]) {
    #pragma unroll
    for (int i = 0; i < 4; ++i)
        #pragma unroll
        for (int j = 0; j < 4; ++j) acc[i][j] = make_float2(0.f, 0.f);

    float2 W[4][6];
    #pragma unroll
    for (int j = 0; j < 4; ++j) {
        const float* p = base + j * stride;
        float4 a = *(const float4*)p, bb = *(const float4*)(p + 4), c = *(const float4*)(p + 8);
        W[j][0] = make_float2(a.x, a.y);   W[j][1] = make_float2(a.z, a.w);
        W[j][2] = make_float2(bb.x, bb.y); W[j][3] = make_float2(bb.z, bb.w);
        W[j][4] = make_float2(c.x, c.y);   W[j][5] = make_float2(c.z, c.w);
    }
    #pragma unroll
    for (int t = 0; t < 9; ++t) {
        const float2* fp = &sfp[t * 10];
        float2 fe0 = fp[0], fe1 = fp[1], fe2 = fp[2], fe3 = fp[3], fe4 = fp[4];
        float2 fo0 = fp[5], fo1 = fp[6], fo2 = fp[7], fo3 = fp[8], f0z = fp[9];
        #pragma unroll
        for (int oy = 0; oy < 4; ++oy) {
            float2* w = W[(t + oy) & 3];
            ffma2(acc[oy][0], fe0, w[0]); ffma2(acc[oy][0], fe1, w[1]);
            ffma2(acc[oy][0], fe2, w[2]); ffma2(acc[oy][0], fe3, w[3]);
            ffma2(acc[oy][0], fe4, w[4]);
            ffma2(acc[oy][2], fe0, w[1]); ffma2(acc[oy][2], fe1, w[2]);
            ffma2(acc[oy][2], fe2, w[3]); ffma2(acc[oy][2], fe3, w[4]);
            ffma2(acc[oy][2], fe4, w[5]);
            ffma2(acc[oy][1], f0z, w[0]); ffma2(acc[oy][1], fo0, w[1]);
            ffma2(acc[oy][1], fo1, w[2]); ffma2(acc[oy][1], fo2, w[3]);
            ffma2(acc[oy][1], fo3, w[4]);
            ffma2(acc[oy][3], f0z, w[1]); ffma2(acc[oy][3], fo0, w[2]);
            ffma2(acc[oy][3], fo1, w[3]); ffma2(acc[oy][3], fo2, w[4]);
            ffma2(acc[oy][3], fo3, w[5]);
        }
        if (t < 8) {
            const float* p = base + (t + 4) * stride;
            float4 a = *(const float4*)p, bb = *(const float4*)(p + 4), c = *(const float4*)(p + 8);
            float2* w = W[t & 3];
            w[0] = make_float2(a.x, a.y);   w[1] = make_float2(a.z, a.w);
            w[2] = make_float2(bb.x, bb.y); w[3] = make_float2(bb.z, bb.w);
            w[4] = make_float2(c.x, c.y);   w[5] = make_float2(c.z, c.w);
        }
    }
}

// ---------------------------------------------------------------------------
// Fused kernel: filter normalize + S1/S2 + conv0 (72x72, in smem) + t
//               + conv1 (64x64) -> sigma, m, block partial sums.
// Block 256 threads, 64x64 outputs, grid (8, 8, NB).
// ---------------------------------------------------------------------------
__global__ void __launch_bounds__(256) k_fused(const float* __restrict__ x,
                                               const float* __restrict__ filt) {
    __shared__ float  tileA[80 * 80];   // S1, stride 80
    __shared__ float  tileB[72 * 76];   // S2, then t, stride 76
    __shared__ float2 sfp[90];
    __shared__ float  red[3];
    __shared__ float  wsum[8];

    const int b   = blockIdx.z;
    const int bx  = blockIdx.x;
    const int by  = blockIdx.y;
    const int tid = threadIdx.x;
    const int x0  = bx * 64 - 8;        // S1 tile origin
    const int y0  = by * 64 - 8;

    // ---- inline filter sum (threads 0..95, 3 warps) ----
    if (tid < 96) {
        float v = (tid < 81) ? (__ldg(&filt[tid]) + 10.0f) : 0.0f;
        #pragma unroll
        for (int o = 16; o; o >>= 1) v += __shfl_xor_sync(0xffffffffu, v, o);
        if ((tid & 31) == 0) red[tid >> 5] = v;
    }
    __syncthreads();
    {
        float inv = 1.0f / (red[0] + red[1] + red[2]);
        if (tid < 90) {
            int r = tid / 10, k = tid - r * 10;
            const float* f = filt + r * 9;
            float2 o;
            if (k < 5) {
                float a = (__ldg(&f[2 * k]) + 10.0f) * inv;
                float bb = (2 * k + 1 < 9) ? (__ldg(&f[2 * k + 1]) + 10.0f) * inv : 0.0f;
                o = make_float2(a, bb);
            } else if (k < 9) {
                int j = k - 5;
                o = make_float2((__ldg(&f[2 * j + 1]) + 10.0f) * inv,
                                (__ldg(&f[2 * j + 2]) + 10.0f) * inv);
            } else {
                o = make_float2(0.0f, (__ldg(&f[0]) + 10.0f) * inv);
            }
            sfp[tid] = o;
        }
    }

    // ---- load x tile: S1 (80x80) + S2 (center 72x72) ----
    for (int i = tid; i < 80 * 20; i += 256) {
        int row = i / 20, q = i - row * 20;
        int gy = y0 + row, gx = x0 + q * 4;
        float4 a = make_float4(0.f, 0.f, 0.f, 0.f), bb = a, c = a;
        if ((unsigned)gy < (unsigned)HW && (unsigned)gx < (unsigned)HW) {
            const float4* p = (const float4*)x +
                (((size_t)b * PLANE + (size_t)gy * HW + gx) >> 2) * 3;
            a = p[0]; bb = p[1]; c = p[2];
        }
        float4 s1, s2;
        s1.x = a.x + a.y + a.z;   s2.x = a.x*a.x + a.y*a.y + a.z*a.z;
        s1.y = a.w + bb.x + bb.y; s2.y = a.w*a.w + bb.x*bb.x + bb.y*bb.y;
        s1.z = bb.z + bb.w + c.x; s2.z = bb.z*bb.z + bb.w*bb.w + c.x*c.x;
        s1.w = c.y + c.z + c.w;   s2.w = c.y*c.y + c.z*c.z + c.w*c.w;
        *(float4*)&tileA[row * 80 + q * 4] = s1;
        if (row >= 4 && row < 76 && q >= 1 && q < 19)
            *(float4*)&tileB[(row - 4) * 76 + (q - 1) * 4] = s2;
    }
    __syncthreads();

    // ---- phase B: conv0 at 72x72 t-points; t = S2 - 2 m S1 + 3 m^2 (in-place) ----
    #pragma unroll 1
    for (int pass = 0; pass < 2; ++pass) {
        int tt = tid + pass * 256;
        if (tt < 324) {
            int ti = tt % 18, tj = tt / 18;
            float2 acc[4][4];
            conv16(&tileA[(tj * 4) * 80 + ti * 4], 80, sfp, acc);
            int gx0 = bx * 64 - 4 + ti * 4;
            bool vx0 = (unsigned)(gx0 + 0) < (unsigned)HW;
            bool vx1 = (unsigned)(gx0 + 1) < (unsigned)HW;
            bool vx2 = (unsigned)(gx0 + 2) < (unsigned)HW;
            bool vx3 = (unsigned)(gx0 + 3) < (unsigned)HW;
            bool mcol = (ti >= 1 && ti < 17);
            #pragma unroll
            for (int oy = 0; oy < 4; ++oy) {
                int r  = tj * 4 + oy;
                int gy = by * 64 - 4 + r;
                bool vy = (unsigned)gy < (unsigned)HW;
                float m0 = acc[oy][0].x + acc[oy][0].y;
                float m1 = acc[oy][1].x + acc[oy][1].y;
                float m2 = acc[oy][2].x + acc[oy][2].y;
                float m3 = acc[oy][3].x + acc[oy][3].y;
                float4 s2 = *(const float4*)&tileB[r * 76 + ti * 4];
                float4 s1 = *(const float4*)&tileA[(r + 4) * 80 + ti * 4 + 4];
                float4 t4;
                t4.x = (vy && vx0) ? s2.x - 2.0f*m0*s1.x + 3.0f*m0*m0 : 0.0f;
                t4.y = (vy && vx1) ? s2.y - 2.0f*m1*s1.y + 3.0f*m1*m1 : 0.0f;
                t4.z = (vy && vx2) ? s2.z - 2.0f*m2*s1.z + 3.0f*m2*m2 : 0.0f;
                t4.w = (vy && vx3) ? s2.w - 2.0f*m3*s1.w + 3.0f*m3*m3 : 0.0f;
                *(float4*)&tileB[r * 76 + ti * 4] = t4;
                if (mcol && r >= 4 && r < 68) {
                    size_t q = ((size_t)b * PLANE +
                                (size_t)(by * 64 + r - 4) * HW + (gx0 + 4 - 4)) >> 2;
                    ((float4*)g_M)[q] = make_float4(m0, m1, m2, m3);
                }
            }
        }
    }
    __syncthreads();

    // ---- phase C: conv1 over t -> sigma + partial sums ----
    {
        const int tx = tid & 15;
        const int ty = tid >> 4;
        float2 acc[4][4];
        conv16(&tileB[(ty * 4) * 76 + tx * 4], 76, sfp, acc);

        const int ox = bx * 64 + tx * 4;
        float local = 0.0f;
        #pragma unroll
        for (int oy = 0; oy < 4; ++oy) {
            int oyg = by * 64 + ty * 4 + oy;
            size_t q = ((size_t)b * PLANE + (size_t)oyg * HW + ox) >> 2;
            float4 sg;
            sg.x = sqrtf(fmaxf(acc[oy][0].x + acc[oy][0].y, 0.0f));
            sg.y = sqrtf(fmaxf(acc[oy][1].x + acc[oy][1].y, 0.0f));
            sg.z = sqrtf(fmaxf(acc[oy][2].x + acc[oy][2].y, 0.0f));
            sg.w = sqrtf(fmaxf(acc[oy][3].x + acc[oy][3].y, 0.0f));
            ((float4*)g_S)[q] = sg;
            local += sg.x + sg.y + sg.z + sg.w;
        }
        #pragma unroll
        for (int o = 16; o; o >>= 1) local += __shfl_xor_sync(0xffffffffu, local, o);
        if ((tid & 31) == 0) wsum[tid >> 5] = local;
        __syncthreads();
        if (tid == 0) {
            float s = 0.0f;
            #pragma unroll
            for (int k = 0; k < 8; ++k) s += wsum[k];
            g_part[b * 64 + by * 8 + bx] = s;
        }
    }
}

// ---------------------------------------------------------------------------
// Final: per-block redundant mean reduce (64 partials) + normalize + write out
// Block = 256 threads = 256 pixel-quads; 256 blocks per batch.
// ---------------------------------------------------------------------------
__global__ void __launch_bounds__(256) k_final(const float* __restrict__ x,
                                               float* __restrict__ out) {
    __shared__ float ws[2];
    __shared__ float smean;
    const int tid = threadIdx.x;
    const int b   = blockIdx.x >> 8;            // 256 blocks per batch

    if (tid < 64) {
        float v = g_part[b * 64 + tid];
        #pragma unroll
        for (int o = 16; o; o >>= 1) v += __shfl_xor_sync(0xffffffffu, v, o);
        if ((tid & 31) == 0) ws[tid >> 5] = v;
    }
    __syncthreads();
    if (tid == 0) smean = (ws[0] + ws[1]) * (1.0f / (float)PLANE);
    __syncthreads();
    const float mean = smean;

    int i = blockIdx.x * 256 + tid;              // pixel-quad index
    float4 m  = ((const float4*)g_M)[i];
    float4 sg = ((const float4*)g_S)[i];
    float r0 = 1.0f / fmaxf(mean, sg.x);
    float r1 = 1.0f / fmaxf(mean, sg.y);
    float r2 = 1.0f / fmaxf(mean, sg.z);
    float r3 = 1.0f / fmaxf(mean, sg.w);

    const float4* xp = (const float4*)x;
    float4 a  = xp[i * 3 + 0];
    float4 bb = xp[i * 3 + 1];
    float4 c  = xp[i * 3 + 2];

    float4 o0, o1, o2;
    o0.x = (a.x  - m.x) * r0;  o0.y = (a.y  - m.x) * r0;  o0.z = (a.z  - m.x) * r0;
    o0.w = (a.w  - m.y) * r1;
    o1.x = (bb.x - m.y) * r1;  o1.y = (bb.y - m.y) * r1;
    o1.z = (bb.z - m.z) * r2;  o1.w = (bb.w - m.z) * r2;
    o2.x = (c.x  - m.z) * r2;
    o2.y = (c.y  - m.w) * r3;  o2.z = (c.z  - m.w) * r3;  o2.w = (c.w  - m.w) * r3;

    float4* op = (float4*)out;
    op[i * 3 + 0] = o0;
    op[i * 3 + 1] = o1;
    op[i * 3 + 2] = o2;
}

// ---------------------------------------------------------------------------
extern "C" void kernel_launch(void* const* d_in, const int* in_sizes, int n_in,
                              void* d_out, int out_size) {
    const float* x    = (const float*)d_in[0];
    const float* filt = (const float*)d_in[1];
    float* out        = (float*)d_out;

    dim3 cgrid(8, 8, NB);
    k_fused<<<cgrid, 256>>>(x, filt);
    k_final<<<NPIX / 1024, 256>>>(x, out);
}

// round 8
// speedup vs baseline: 1.0073x; 1.0003x over previous
#include <cuda_runtime.h>

#define HW     512
#define NB     16
#define PLANE  (HW * HW)          // 262144
#define NPIX   (NB * PLANE)       // 4194304

// Global scratch (2 planes + small reductions)
__device__ float g_M[NPIX];        // local mean m
__device__ float g_S[NPIX];        // sigma
__device__ float g_part[NB * 64];  // per-block sigma partial sums (8x8 blocks/batch)

// packed fp32x2 FMA: d += a * b (two independent lanes)
__device__ __forceinline__ void ffma2(float2 &d, const float2 a, const float2 b) {
    asm("fma.rn.f32x2 %0, %1, %2, %0;"
        : "+l"(reinterpret_cast<unsigned long long &>(d))
        : "l"(reinterpret_cast<const unsigned long long &>(a)),
          "l"(reinterpret_cast<const unsigned long long &>(b)));
}

// 4x4-output 9x9 conv micro-tile with packed filter pairs + 4-row sliding window.
// base points at input tile element (row0, col0); stride in floats.
// sfp layout per tap-row t: [0..4]=(f2k,f2k+1), [5..8]=(f2k+1,f2k+2), [9]=(0,f0)
__device__ __forceinline__ void conv16(const float* base, const int stride,
                                       const float2* __restrict__ sfp,
                                       float2 acc[4][4]) {
    #pragma unroll
    for (int i = 0; i < 4; ++i)
        #pragma unroll
        for (int j = 0; j < 4; ++j) acc[i][j] = make_float2(0.f, 0.f);

    float2 W[4][6];
    #pragma unroll
    for (int j = 0; j < 4; ++j) {
        const float* p = base + j * stride;
        float4 a = *(const float4*)p, bb = *(const float4*)(p + 4), c = *(const float4*)(p + 8);
        W[j][0] = make_float2(a.x, a.y);   W[j][1] = make_float2(a.z, a.w);
        W[j][2] = make_float2(bb.x, bb.y); W[j][3] = make_float2(bb.z, bb.w);
        W[j][4] = make_float2(c.x, c.y);   W[j][5] = make_float2(c.z, c.w);
    }
    #pragma unroll
    for (int t = 0; t < 9; ++t) {
        const float2* fp = &sfp[t * 10];
        float2 fe0 = fp[0], fe1 = fp[1], fe2 = fp[2], fe3 = fp[3], fe4 = fp[4];
        float2 fo0 = fp[5], fo1 = fp[6], fo2 = fp[7], fo3 = fp[8], f0z = fp[9];
        #pragma unroll
        for (int oy = 0; oy < 4; ++oy) {
            float2* w = W[(t + oy) & 3];
            ffma2(acc[oy][0], fe0, w[0]); ffma2(acc[oy][0], fe1, w[1]);
            ffma2(acc[oy][0], fe2, w[2]); ffma2(acc[oy][0], fe3, w[3]);
            ffma2(acc[oy][0], fe4, w[4]);
            ffma2(acc[oy][2], fe0, w[1]); ffma2(acc[oy][2], fe1, w[2]);
            ffma2(acc[oy][2], fe2, w[3]); ffma2(acc[oy][2], fe3, w[4]);
            ffma2(acc[oy][2], fe4, w[5]);
            ffma2(acc[oy][1], f0z, w[0]); ffma2(acc[oy][1], fo0, w[1]);
            ffma2(acc[oy][1], fo1, w[2]); ffma2(acc[oy][1], fo2, w[3]);
            ffma2(acc[oy][1], fo3, w[4]);
            ffma2(acc[oy][3], f0z, w[1]); ffma2(acc[oy][3], fo0, w[2]);
            ffma2(acc[oy][3], fo1, w[3]); ffma2(acc[oy][3], fo2, w[4]);
            ffma2(acc[oy][3], fo3, w[5]);
        }
        if (t < 8) {
            const float* p = base + (t + 4) * stride;
            float4 a = *(const float4*)p, bb = *(const float4*)(p + 4), c = *(const float4*)(p + 8);
            float2* w = W[t & 3];
            w[0] = make_float2(a.x, a.y);   w[1] = make_float2(a.z, a.w);
            w[2] = make_float2(bb.x, bb.y); w[3] = make_float2(bb.z, bb.w);
            w[4] = make_float2(c.x, c.y);   w[5] = make_float2(c.z, c.w);
        }
    }
}

// ---------------------------------------------------------------------------
// Fused kernel: filter normalize + S1/S2 + conv0 (72x72, in smem) + t
//               + conv1 (64x64) -> sigma, m, block partial sums.
// Block 256 threads, 64x64 outputs, grid (8, 8, NB).
// ---------------------------------------------------------------------------
__global__ void __launch_bounds__(256) k_fused(const float* __restrict__ x,
                                               const float* __restrict__ filt) {
    __shared__ float  tileA[80 * 80];   // S1, stride 80
    __shared__ float  tileB[72 * 76];   // S2, then t, stride 76
    __shared__ float2 sfp[90];
    __shared__ float  red[3];
    __shared__ float  wsum[8];

    const int b   = blockIdx.z;
    const int bx  = blockIdx.x;
    const int by  = blockIdx.y;
    const int tid = threadIdx.x;
    const int x0  = bx * 64 - 8;        // S1 tile origin
    const int y0  = by * 64 - 8;

    // ---- inline filter sum (threads 0..95, 3 warps) ----
    if (tid < 96) {
        float v = (tid < 81) ? (__ldg(&filt[tid]) + 10.0f) : 0.0f;
        #pragma unroll
        for (int o = 16; o; o >>= 1) v += __shfl_xor_sync(0xffffffffu, v, o);
        if ((tid & 31) == 0) red[tid >> 5] = v;
    }
    __syncthreads();
    {
        float inv = 1.0f / (red[0] + red[1] + red[2]);
        if (tid < 90) {
            int r = tid / 10, k = tid - r * 10;
            const float* f = filt + r * 9;
            float2 o;
            if (k < 5) {
                float a = (__ldg(&f[2 * k]) + 10.0f) * inv;
                float bb = (2 * k + 1 < 9) ? (__ldg(&f[2 * k + 1]) + 10.0f) * inv : 0.0f;
                o = make_float2(a, bb);
            } else if (k < 9) {
                int j = k - 5;
                o = make_float2((__ldg(&f[2 * j + 1]) + 10.0f) * inv,
                                (__ldg(&f[2 * j + 2]) + 10.0f) * inv);
            } else {
                o = make_float2(0.0f, (__ldg(&f[0]) + 10.0f) * inv);
            }
            sfp[tid] = o;
        }
    }

    // ---- load x tile: S1 (80x80) + S2 (center 72x72) ----
    for (int i = tid; i < 80 * 20; i += 256) {
        int row = i / 20, q = i - row * 20;
        int gy = y0 + row, gx = x0 + q * 4;
        float4 a = make_float4(0.f, 0.f, 0.f, 0.f), bb = a, c = a;
        if ((unsigned)gy < (unsigned)HW && (unsigned)gx < (unsigned)HW) {
            const float4* p = (const float4*)x +
                (((size_t)b * PLANE + (size_t)gy * HW + gx) >> 2) * 3;
            a = p[0]; bb = p[1]; c = p[2];
        }
        float4 s1, s2;
        s1.x = a.x + a.y + a.z;   s2.x = a.x*a.x + a.y*a.y + a.z*a.z;
        s1.y = a.w + bb.x + bb.y; s2.y = a.w*a.w + bb.x*bb.x + bb.y*bb.y;
        s1.z = bb.z + bb.w + c.x; s2.z = bb.z*bb.z + bb.w*bb.w + c.x*c.x;
        s1.w = c.y + c.z + c.w;   s2.w = c.y*c.y + c.z*c.z + c.w*c.w;
        *(float4*)&tileA[row * 80 + q * 4] = s1;
        if (row >= 4 && row < 76 && q >= 1 && q < 19)
            *(float4*)&tileB[(row - 4) * 76 + (q - 1) * 4] = s2;
    }
    __syncthreads();

    // ---- phase B: conv0 at 72x72 t-points; t = S2 - 2 m S1 + 3 m^2 (in-place) ----
    #pragma unroll 1
    for (int pass = 0; pass < 2; ++pass) {
        int tt = tid + pass * 256;
        if (tt < 324) {
            int ti = tt % 18, tj = tt / 18;
            float2 acc[4][4];
            conv16(&tileA[(tj * 4) * 80 + ti * 4], 80, sfp, acc);
            int gx0 = bx * 64 - 4 + ti * 4;
            bool vx0 = (unsigned)(gx0 + 0) < (unsigned)HW;
            bool vx1 = (unsigned)(gx0 + 1) < (unsigned)HW;
            bool vx2 = (unsigned)(gx0 + 2) < (unsigned)HW;
            bool vx3 = (unsigned)(gx0 + 3) < (unsigned)HW;
            bool mcol = (ti >= 1 && ti < 17);
            #pragma unroll
            for (int oy = 0; oy < 4; ++oy) {
                int r  = tj * 4 + oy;
                int gy = by * 64 - 4 + r;
                bool vy = (unsigned)gy < (unsigned)HW;
                float m0 = acc[oy][0].x + acc[oy][0].y;
                float m1 = acc[oy][1].x + acc[oy][1].y;
                float m2 = acc[oy][2].x + acc[oy][2].y;
                float m3 = acc[oy][3].x + acc[oy][3].y;
                float4 s2 = *(const float4*)&tileB[r * 76 + ti * 4];
                float4 s1 = *(const float4*)&tileA[(r + 4) * 80 + ti * 4 + 4];
                float4 t4;
                t4.x = (vy && vx0) ? s2.x - 2.0f*m0*s1.x + 3.0f*m0*m0 : 0.0f;
                t4.y = (vy && vx1) ? s2.y - 2.0f*m1*s1.y + 3.0f*m1*m1 : 0.0f;
                t4.z = (vy && vx2) ? s2.z - 2.0f*m2*s1.z + 3.0f*m2*m2 : 0.0f;
                t4.w = (vy && vx3) ? s2.w - 2.0f*m3*s1.w + 3.0f*m3*m3 : 0.0f;
                *(float4*)&tileB[r * 76 + ti * 4] = t4;
                if (mcol && r >= 4 && r < 68) {
                    size_t q = ((size_t)b * PLANE +
                                (size_t)(by * 64 + r - 4) * HW + (gx0 + 4 - 4)) >> 2;
                    ((float4*)g_M)[q] = make_float4(m0, m1, m2, m3);
                }
            }
        }
    }
    __syncthreads();

    // ---- phase C: conv1 over t -> sigma + partial sums ----
    {
        const int tx = tid & 15;
        const int ty = tid >> 4;
        float2 acc[4][4];
        conv16(&tileB[(ty * 4) * 76 + tx * 4], 76, sfp, acc);

        const int ox = bx * 64 + tx * 4;
        float local = 0.0f;
        #pragma unroll
        for (int oy = 0; oy < 4; ++oy) {
            int oyg = by * 64 + ty * 4 + oy;
            size_t q = ((size_t)b * PLANE + (size_t)oyg * HW + ox) >> 2;
            float4 sg;
            sg.x = sqrtf(fmaxf(acc[oy][0].x + acc[oy][0].y, 0.0f));
            sg.y = sqrtf(fmaxf(acc[oy][1].x + acc[oy][1].y, 0.0f));
            sg.z = sqrtf(fmaxf(acc[oy][2].x + acc[oy][2].y, 0.0f));
            sg.w = sqrtf(fmaxf(acc[oy][3].x + acc[oy][3].y, 0.0f));
            ((float4*)g_S)[q] = sg;
            local += sg.x + sg.y + sg.z + sg.w;
        }
        #pragma unroll
        for (int o = 16; o; o >>= 1) local += __shfl_xor_sync(0xffffffffu, local, o);
        if ((tid & 31) == 0) wsum[tid >> 5] = local;
        __syncthreads();
        if (tid == 0) {
            float s = 0.0f;
            #pragma unroll
            for (int k = 0; k < 8; ++k) s += wsum[k];
            g_part[b * 64 + by * 8 + bx] = s;
        }
    }
}

// ---------------------------------------------------------------------------
// Final: per-block redundant mean reduce (64 partials) + normalize + write out
// Block = 256 threads = 256 pixel-quads; 256 blocks per batch.
// ---------------------------------------------------------------------------
__global__ void __launch_bounds__(256) k_final(const float* __restrict__ x,
                                               float* __restrict__ out) {
    __shared__ float ws[2];
    __shared__ float smean;
    const int tid = threadIdx.x;
    const int b   = blockIdx.x >> 8;            // 256 blocks per batch

    if (tid < 64) {
        float v = g_part[b * 64 + tid];
        #pragma unroll
        for (int o = 16; o; o >>= 1) v += __shfl_xor_sync(0xffffffffu, v, o);
        if ((tid & 31) == 0) ws[tid >> 5] = v;
    }
    __syncthreads();
    if (tid == 0) smean = (ws[0] + ws[1]) * (1.0f / (float)PLANE);
    __syncthreads();
    const float mean = smean;

    int i = blockIdx.x * 256 + tid;              // pixel-quad index
    float4 m  = ((const float4*)g_M)[i];
    float4 sg = ((const float4*)g_S)[i];
    float r0 = 1.0f / fmaxf(mean, sg.x);
    float r1 = 1.0f / fmaxf(mean, sg.y);
    float r2 = 1.0f / fmaxf(mean, sg.z);
    float r3 = 1.0f / fmaxf(mean, sg.w);

    const float4* xp = (const float4*)x;
    float4 a  = xp[i * 3 + 0];
    float4 bb = xp[i * 3 + 1];
    float4 c  = xp[i * 3 + 2];

    float4 o0, o1, o2;
    o0.x = (a.x  - m.x) * r0;  o0.y = (a.y  - m.x) * r0;  o0.z = (a.z  - m.x) * r0;
    o0.w = (a.w  - m.y) * r1;
    o1.x = (bb.x - m.y) * r1;  o1.y = (bb.y - m.y) * r1;
    o1.z = (bb.z - m.z) * r2;  o1.w = (bb.w - m.z) * r2;
    o2.x = (c.x  - m.z) * r2;
    o2.y = (c.y  - m.w) * r3;  o2.z = (c.z  - m.w) * r3;  o2.w = (c.w  - m.w) * r3;

    float4* op = (float4*)out;
    op[i * 3 + 0] = o0;
    op[i * 3 + 1] = o1;
    op[i * 3 + 2] = o2;
}

// ---------------------------------------------------------------------------
extern "C" void kernel_launch(void* const* d_in, const int* in_sizes, int n_in,
                              void* d_out, int out_size) {
    const float* x    = (const float*)d_in[0];
    const float* filt = (const float*)d_in[1];
    float* out        = (float*)d_out;

    dim3 cgrid(8, 8, NB);
    k_fused<<<cgrid, 256>>>(x, filt);
    k_final<<<NPIX / 1024, 256>>>(x, out);
}

// round 9
// speedup vs baseline: 1.0115x; 1.0041x over previous
#include <cuda_runtime.h>

#define HW     512
#define NB     16
#define PLANE  (HW * HW)          // 262144
#define NPIX   (NB * PLANE)       // 4194304

// Global scratch (2 planes + small reductions)
__device__ float g_M[NPIX];        // local mean m
__device__ float g_S[NPIX];        // sigma
__device__ float g_part[NB * 64];  // per-block sigma partial sums (8x8 blocks/batch)

// packed fp32x2 FMA: d += a * b (two independent lanes)
__device__ __forceinline__ void ffma2(float2 &d, const float2 a, const float2 b) {
    asm("fma.rn.f32x2 %0, %1, %2, %0;"
        : "+l"(reinterpret_cast<unsigned long long &>(d))
        : "l"(reinterpret_cast<const unsigned long long &>(a)),
          "l"(reinterpret_cast<const unsigned long long &>(b)));
}

// 4x4-output 9x9 conv micro-tile with packed filter pairs + 4-row sliding window.
// base points at input tile element (row0, col0); stride in floats.
// sfp layout per tap-row t: [0..4]=(f2k,f2k+1), [5..8]=(f2k+1,f2k+2), [9]=(0,f0)
__device__ __forceinline__ void conv16(const float* base, const int stride,
                                       const float2* __restrict__ sfp,
                                       float2 acc[4][4]) {
    #pragma unroll
    for (int i = 0; i < 4; ++i)
        #pragma unroll
        for (int j = 0; j < 4; ++j) acc[i][j] = make_float2(0.f, 0.f);

    float2 W[4][6];
    #pragma unroll
    for (int j = 0; j < 4; ++j) {
        const float* p = base + j * stride;
        float4 a = *(const float4*)p, bb = *(const float4*)(p + 4), c = *(const float4*)(p + 8);
        W[j][0] = make_float2(a.x, a.y);   W[j][1] = make_float2(a.z, a.w);
        W[j][2] = make_float2(bb.x, bb.y); W[j][3] = make_float2(bb.z, bb.w);
        W[j][4] = make_float2(c.x, c.y);   W[j][5] = make_float2(c.z, c.w);
    }
    #pragma unroll
    for (int t = 0; t < 9; ++t) {
        const float2* fp = &sfp[t * 10];
        float2 fe0 = fp[0], fe1 = fp[1], fe2 = fp[2], fe3 = fp[3], fe4 = fp[4];
        float2 fo0 = fp[5], fo1 = fp[6], fo2 = fp[7], fo3 = fp[8], f0z = fp[9];
        #pragma unroll
        for (int oy = 0; oy < 4; ++oy) {
            float2* w = W[(t + oy) & 3];
            ffma2(acc[oy][0], fe0, w[0]); ffma2(acc[oy][0], fe1, w[1]);
            ffma2(acc[oy][0], fe2, w[2]); ffma2(acc[oy][0], fe3, w[3]);
            ffma2(acc[oy][0], fe4, w[4]);
            ffma2(acc[oy][2], fe0, w[1]); ffma2(acc[oy][2], fe1, w[2]);
            ffma2(acc[oy][2], fe2, w[3]); ffma2(acc[oy][2], fe3, w[4]);
            ffma2(acc[oy][2], fe4, w[5]);
            ffma2(acc[oy][1], f0z, w[0]); ffma2(acc[oy][1], fo0, w[1]);
            ffma2(acc[oy][1], fo1, w[2]); ffma2(acc[oy][1], fo2, w[3]);
            ffma2(acc[oy][1], fo3, w[4]);
            ffma2(acc[oy][3], f0z, w[1]); ffma2(acc[oy][3], fo0, w[2]);
            ffma2(acc[oy][3], fo1, w[3]); ffma2(acc[oy][3], fo2, w[4]);
            ffma2(acc[oy][3], fo3, w[5]);
        }
        if (t < 8) {
            const float* p = base + (t + 4) * stride;
            float4 a = *(const float4*)p, bb = *(const float4*)(p + 4), c = *(const float4*)(p + 8);
            float2* w = W[t & 3];
            w[0] = make_float2(a.x, a.y);   w[1] = make_float2(a.z, a.w);
            w[2] = make_float2(bb.x, bb.y); w[3] = make_float2(bb.z, bb.w);
            w[4] = make_float2(c.x, c.y);   w[5] = make_float2(c.z, c.w);
        }
    }
}

// ---------------------------------------------------------------------------
// Fused kernel: filter normalize + S1/S2 + conv0 (72x72, in smem) + t
//               + conv1 (64x64) -> sigma, m, block partial sums.
// Block 256 threads, 64x64 outputs, grid (8, 8, NB).
// ---------------------------------------------------------------------------
__global__ void __launch_bounds__(256) k_fused(const float* __restrict__ x,
                                               const float* __restrict__ filt) {
    __shared__ float  tileA[80 * 80];   // S1, stride 80
    __shared__ float  tileB[72 * 76];   // S2, then t, stride 76
    __shared__ float2 sfp[90];
    __shared__ float  red[3];
    __shared__ float  wsum[8];

    const int b   = blockIdx.z;
    const int bx  = blockIdx.x;
    const int by  = blockIdx.y;
    const int tid = threadIdx.x;
    const int x0  = bx * 64 - 8;        // S1 tile origin
    const int y0  = by * 64 - 8;

    // ---- inline filter sum (threads 0..95, 3 warps) ----
    if (tid < 96) {
        float v = (tid < 81) ? (__ldg(&filt[tid]) + 10.0f) : 0.0f;
        #pragma unroll
        for (int o = 16; o; o >>= 1) v += __shfl_xor_sync(0xffffffffu, v, o);
        if ((tid & 31) == 0) red[tid >> 5] = v;
    }
    __syncthreads();
    {
        float inv = 1.0f / (red[0] + red[1] + red[2]);
        if (tid < 90) {
            int r = tid / 10, k = tid - r * 10;
            const float* f = filt + r * 9;
            float2 o;
            if (k < 5) {
                float a = (__ldg(&f[2 * k]) + 10.0f) * inv;
                float bb = (2 * k + 1 < 9) ? (__ldg(&f[2 * k + 1]) + 10.0f) * inv : 0.0f;
                o = make_float2(a, bb);
            } else if (k < 9) {
                int j = k - 5;
                o = make_float2((__ldg(&f[2 * j + 1]) + 10.0f) * inv,
                                (__ldg(&f[2 * j + 2]) + 10.0f) * inv);
            } else {
                o = make_float2(0.0f, (__ldg(&f[0]) + 10.0f) * inv);
            }
            sfp[tid] = o;
        }
    }

    // ---- load x tile: S1 (80x80) + S2 (center 72x72) ----
    for (int i = tid; i < 80 * 20; i += 256) {
        int row = i / 20, q = i - row * 20;
        int gy = y0 + row, gx = x0 + q * 4;
        float4 a = make_float4(0.f, 0.f, 0.f, 0.f), bb = a, c = a;
        if ((unsigned)gy < (unsigned)HW && (unsigned)gx < (unsigned)HW) {
            const float4* p = (const float4*)x +
                (((size_t)b * PLANE + (size_t)gy * HW + gx) >> 2) * 3;
            a = p[0]; bb = p[1]; c = p[2];
        }
        float4 s1, s2;
        s1.x = a.x + a.y + a.z;   s2.x = a.x*a.x + a.y*a.y + a.z*a.z;
        s1.y = a.w + bb.x + bb.y; s2.y = a.w*a.w + bb.x*bb.x + bb.y*bb.y;
        s1.z = bb.z + bb.w + c.x; s2.z = bb.z*bb.z + bb.w*bb.w + c.x*c.x;
        s1.w = c.y + c.z + c.w;   s2.w = c.y*c.y + c.z*c.z + c.w*c.w;
        *(float4*)&tileA[row * 80 + q * 4] = s1;
        if (row >= 4 && row < 76 && q >= 1 && q < 19)
            *(float4*)&tileB[(row - 4) * 76 + (q - 1) * 4] = s2;
    }
    __syncthreads();

    // ---- phase B: conv0 at 72x72 t-points; t = S2 - 2 m S1 + 3 m^2 (in-place) ----
    #pragma unroll 1
    for (int pass = 0; pass < 2; ++pass) {
        int tt = tid + pass * 256;
        if (tt < 324) {
            int ti = tt % 18, tj = tt / 18;
            float2 acc[4][4];
            conv16(&tileA[(tj * 4) * 80 + ti * 4], 80, sfp, acc);
            int gx0 = bx * 64 - 4 + ti * 4;
            bool vx0 = (unsigned)(gx0 + 0) < (unsigned)HW;
            bool vx1 = (unsigned)(gx0 + 1) < (unsigned)HW;
            bool vx2 = (unsigned)(gx0 + 2) < (unsigned)HW;
            bool vx3 = (unsigned)(gx0 + 3) < (unsigned)HW;
            bool mcol = (ti >= 1 && ti < 17);
            #pragma unroll
            for (int oy = 0; oy < 4; ++oy) {
                int r  = tj * 4 + oy;
                int gy = by * 64 - 4 + r;
                bool vy = (unsigned)gy < (unsigned)HW;
                float m0 = acc[oy][0].x + acc[oy][0].y;
                float m1 = acc[oy][1].x + acc[oy][1].y;
                float m2 = acc[oy][2].x + acc[oy][2].y;
                float m3 = acc[oy][3].x + acc[oy][3].y;
                float4 s2 = *(const float4*)&tileB[r * 76 + ti * 4];
                float4 s1 = *(const float4*)&tileA[(r + 4) * 80 + ti * 4 + 4];
                float4 t4;
                t4.x = (vy && vx0) ? s2.x - 2.0f*m0*s1.x + 3.0f*m0*m0 : 0.0f;
                t4.y = (vy && vx1) ? s2.y - 2.0f*m1*s1.y + 3.0f*m1*m1 : 0.0f;
                t4.z = (vy && vx2) ? s2.z - 2.0f*m2*s1.z + 3.0f*m2*m2 : 0.0f;
                t4.w = (vy && vx3) ? s2.w - 2.0f*m3*s1.w + 3.0f*m3*m3 : 0.0f;
                *(float4*)&tileB[r * 76 + ti * 4] = t4;
                if (mcol && r >= 4 && r < 68) {
                    size_t q = ((size_t)b * PLANE +
                                (size_t)(by * 64 + r - 4) * HW + (gx0 + 4 - 4)) >> 2;
                    ((float4*)g_M)[q] = make_float4(m0, m1, m2, m3);
                }
            }
        }
    }
    __syncthreads();

    // ---- phase C: conv1 over t -> sigma + partial sums ----
    {
        const int tx = tid & 15;
        const int ty = tid >> 4;
        float2 acc[4][4];
        conv16(&tileB[(ty * 4) * 76 + tx * 4], 76, sfp, acc);

        const int ox = bx * 64 + tx * 4;
        float local = 0.0f;
        #pragma unroll
        for (int oy = 0; oy < 4; ++oy) {
            int oyg = by * 64 + ty * 4 + oy;
            size_t q = ((size_t)b * PLANE + (size_t)oyg * HW + ox) >> 2;
            float4 sg;
            sg.x = sqrtf(fmaxf(acc[oy][0].x + acc[oy][0].y, 0.0f));
            sg.y = sqrtf(fmaxf(acc[oy][1].x + acc[oy][1].y, 0.0f));
            sg.z = sqrtf(fmaxf(acc[oy][2].x + acc[oy][2].y, 0.0f));
            sg.w = sqrtf(fmaxf(acc[oy][3].x + acc[oy][3].y, 0.0f));
            ((float4*)g_S)[q] = sg;
            local += sg.x + sg.y + sg.z + sg.w;
        }
        #pragma unroll
        for (int o = 16; o; o >>= 1) local += __shfl_xor_sync(0xffffffffu, local, o);
        if ((tid & 31) == 0) wsum[tid >> 5] = local;
        __syncthreads();
        if (tid == 0) {
            float s = 0.0f;
            #pragma unroll
            for (int k = 0; k < 8; ++k) s += wsum[k];
            g_part[b * 64 + by * 8 + bx] = s;
        }
    }
}

// ---------------------------------------------------------------------------
// Final: per-block redundant mean reduce (64 partials) + normalize + write out
// Block = 256 threads = 256 pixel-quads; 256 blocks per batch.
// ---------------------------------------------------------------------------
__global__ void __launch_bounds__(256) k_final(const float* __restrict__ x,
                                               float* __restrict__ out) {
    __shared__ float ws[2];
    __shared__ float smean;
    const int tid = threadIdx.x;
    const int b   = blockIdx.x >> 8;            // 256 blocks per batch

    if (tid < 64) {
        float v = g_part[b * 64 + tid];
        #pragma unroll
        for (int o = 16; o; o >>= 1) v += __shfl_xor_sync(0xffffffffu, v, o);
        if ((tid & 31) == 0) ws[tid >> 5] = v;
    }
    __syncthreads();
    if (tid == 0) smean = (ws[0] + ws[1]) * (1.0f / (float)PLANE);
    __syncthreads();
    const float mean = smean;

    int i = blockIdx.x * 256 + tid;              // pixel-quad index
    float4 m  = ((const float4*)g_M)[i];
    float4 sg = ((const float4*)g_S)[i];
    float r0 = 1.0f / fmaxf(mean, sg.x);
    float r1 = 1.0f / fmaxf(mean, sg.y);
    float r2 = 1.0f / fmaxf(mean, sg.z);
    float r3 = 1.0f / fmaxf(mean, sg.w);

    const float4* xp = (const float4*)x;
    float4 a  = xp[i * 3 + 0];
    float4 bb = xp[i * 3 + 1];
    float4 c  = xp[i * 3 + 2];

    float4 o0, o1, o2;
    o0.x = (a.x  - m.x) * r0;  o0.y = (a.y  - m.x) * r0;  o0.z = (a.z  - m.x) * r0;
    o0.w = (a.w  - m.y) * r1;
    o1.x = (bb.x - m.y) * r1;  o1.y = (bb.y - m.y) * r1;
    o1.z = (bb.z - m.z) * r2;  o1.w = (bb.w - m.z) * r2;
    o2.x = (c.x  - m.z) * r2;
    o2.y = (c.y  - m.w) * r3;  o2.z = (c.z  - m.w) * r3;  o2.w = (c.w  - m.w) * r3;

    float4* op = (float4*)out;
    op[i * 3 + 0] = o0;
    op[i * 3 + 1] = o1;
    op[i * 3 + 2] = o2;
}

// ---------------------------------------------------------------------------
extern "C" void kernel_launch(void* const* d_in, const int* in_sizes, int n_in,
                              void* d_out, int out_size) {
    const float* x    = (const float*)d_in[0];
    const float* filt = (const float*)d_in[1];
    float* out        = (float*)d_out;

    dim3 cgrid(8, 8, NB);
    k_fused<<<cgrid, 256>>>(x, filt);
    k_final<<<NPIX / 1024, 256>>>(x, out);
}